// round 13
// baseline (speedup 1.0000x reference)
#include <cuda_runtime.h>
#include <cuda_bf16.h>
#include <math.h>

// ===========================================================================
// MS-SSIM 16x3x512x512 fp32, 5 levels.
// k1_kernel: ssim level-0 blocks + ALL pyramid-pool blocks interleaved 1:3
//   in one grid (pool is independent of ssim L0) -> memory-bound pool traffic
//   overlaps compute-bound ssim instead of serializing in front of it.
// k2_kernel: ssim levels 1-4 + 288 relocated L0 blocks = 1776 blocks
//   (exactly 2.0 waves at 6 CTAs/SM x 148 SMs).
// ssim core: sum/diff transform, packed f32x2 FMA (unchanged from round 12).
// final_kernel: fp32 log2/exp2 combine.
// ===========================================================================

#define OC  128           // output columns per block (== threads)
#define ORR 24            // output rows per block
#define IR  (ORR + 10)    // 34 input rows
#define ICW (OC + 10)     // 138 input cols

// Gaussian taps, sigma=1.5, ws=11
#define G0 0.00102838f
#define G1 0.00759876f
#define G2 0.03600077f
#define G3 0.10936069f
#define G4 0.21300553f
#define G5 0.26601172f

#define C1V 1.0e-4f
#define C2V 9.0e-4f

// Scratch for pooled pyramids
#define S1 (48u * 256u * 256u)
#define S2 (48u * 128u * 128u)
#define S3 (48u * 64u  * 64u)
#define S4 (48u * 32u  * 32u)
#define O1 0u
#define O2 (S1)
#define O3 (S1 + S2)
#define O4 (S1 + S2 + S3)
#define TOT (S1 + S2 + S3 + S4)

// per-level ssim block counts (ORR=24: GY = ceil((H-10)/24))
#define NB0 4032   // 4 x 21 x 48   (H=512)
#define NB1 1056   // 2 x 11 x 48   (H=256)
#define NB2 240    // 1 x  5 x 48   (H=128)
#define NB3 144    // 1 x  3 x 48   (H=64)
#define NB4 48     // 1 x  1 x 48   (H=32)

#define NPOOL 12288              // 48 x 16 x 16 pool tiles
#define K2_SSIM0 288             // L0 blocks relocated into kernel 2
#define K1_SSIM  (NB0 - K2_SSIM0)             // 3744
#define K1_IL    (K1_SSIM * 4)                // 14976 interleaved region
#define K1_GRID  (K1_SSIM + NPOOL)            // 16032
#define K2_GRID  (K2_SSIM0 + NB1 + NB2 + NB3 + NB4)  // 1776 = 2 waves

__device__ float g_p1[TOT];
__device__ float g_p2[TOT];
__device__ double g_acc[10];

// ---- f32x2 packed helpers -------------------------------------------------
typedef unsigned long long ull;
__device__ __forceinline__ ull pk2(float lo, float hi) {
    ull r;
    asm("mov.b64 %0, {%1, %2};" : "=l"(r) : "f"(lo), "f"(hi));
    return r;
}
__device__ __forceinline__ void upk2(ull v, float& lo, float& hi) {
    asm("mov.b64 {%0, %1}, %2;" : "=f"(lo), "=f"(hi) : "l"(v));
}
__device__ __forceinline__ ull fma2(ull a, ull b, ull c) {
    ull d;
    asm("fma.rn.f32x2 %0, %1, %2, %3;" : "=l"(d) : "l"(a), "l"(b), "l"(c));
    return d;
}
__device__ __forceinline__ ull mul2(ull a, ull b) {
    ull d;
    asm("mul.rn.f32x2 %0, %1, %2;" : "=l"(d) : "l"(a), "l"(b));
    return d;
}

// ---- ssim core: one 128-col x 24-row tile of one level ---------------------
__device__ __forceinline__ void ssim_block(
    ull* smem_raw, const float* __restrict__ baseA,
    const float* __restrict__ baseB, int H, int bx, int by, int z, int level)
{
    float2* sUW = reinterpret_cast<float2*>(smem_raw);

    const int tid = threadIdx.x;
    const int rowBase = by * ORR;
    const int colBase = bx * OC;
    const int W = H;
    const size_t zoff = (size_t)z * H * W;
    const float* __restrict__ Ap = baseA + zoff;
    const float* __restrict__ Bp = baseB + zoff;

    // load tile as (u,w) = (a+b, a-b); zero-clamped halo, masked outputs
    for (int i = tid; i < IR * ICW; i += OC) {
        int r = i / ICW;
        int c = i - r * ICW;
        int gr = rowBase + r, gc = colBase + c;
        float u = 0.f, w = 0.f;
        if (gr < H && gc < W) {
            size_t o = (size_t)gr * W + gc;
            float a = __ldg(Ap + o);
            float b = __ldg(Bp + o);
            u = a + b;
            w = a - b;
        }
        sUW[i] = make_float2(u, w);
    }
    __syncthreads();

    const int oc = colBase + tid;
    const bool col_ok = oc < (W - 10);

    ull Gp[6];
    Gp[0] = pk2(G0, G0); Gp[1] = pk2(G1, G1); Gp[2] = pk2(G2, G2);
    Gp[3] = pk2(G3, G3); Gp[4] = pk2(G4, G4); Gp[5] = pk2(G5, G5);

    ull rUW[11], rSQ[11];
    float accS = 0.f, accC = 0.f;

    #pragma unroll
    for (int r = 0; r < IR; r++) {
        // horizontal: 11x (LDS.64 + mul2 + 2x fma2)
        ull sUWa = 0ull, sSQa = 0ull;
        const ull* __restrict__ rowp = smem_raw + r * ICW + tid;
        #pragma unroll
        for (int k = 0; k < 11; k++) {
            ull vp = rowp[k];
            ull g  = Gp[k < 6 ? k : 10 - k];
            sUWa = fma2(vp, g, sUWa);
            sSQa = fma2(mul2(vp, vp), g, sSQa);
        }
        const int slot = r % 11;
        rUW[slot] = sUWa;
        rSQ[slot] = sSQa;

        // vertical: 11x (2x fma2)
        if (r >= 10) {
            ull mUW = 0ull, mSQ = 0ull;
            #pragma unroll
            for (int j = 0; j < 11; j++) {
                const int sl = (r - 10 + j) % 11;
                ull g = Gp[j < 6 ? j : 10 - j];
                mUW = fma2(rUW[sl], g, mUW);
                mSQ = fma2(rSQ[sl], g, mSQ);
            }
            int gr = rowBase + r;
            if (col_ok && gr < H) {
                float cU2, cW2, p, q;
                upk2(mSQ, cU2, cW2);
                ull pq = mul2(mUW, mUW);
                upk2(pq, p, q);
                float n1 = 0.5f * (p - q) + C1V;
                float d1 = 0.5f * (p + q) + C1V;
                float v1 = 0.5f * ((cU2 - cW2) - (p - q)) + C2V;
                float v2 = 0.5f * ((cU2 + cW2) - (p + q)) + C2V;
                float cs = __fdividef(v1, v2);
                float ssim = cs * __fdividef(n1, d1);
                accS += ssim;
                accC += cs;
            }
        }
    }

    // block reduction
    #pragma unroll
    for (int off = 16; off > 0; off >>= 1) {
        accS += __shfl_down_sync(0xFFFFFFFFu, accS, off);
        accC += __shfl_down_sync(0xFFFFFFFFu, accC, off);
    }
    __shared__ float wS[OC / 32], wC[OC / 32];
    const int warp = tid >> 5, lane = tid & 31;
    if (lane == 0) { wS[warp] = accS; wC[warp] = accC; }
    __syncthreads();
    if (tid == 0) {
        float bs = 0.f, bc = 0.f;
        #pragma unroll
        for (int wi = 0; wi < OC / 32; wi++) { bs += wS[wi]; bc += wC[wi]; }
        atomicAdd(&g_acc[2 * level],     (double)bs);
        atomicAdd(&g_acc[2 * level + 1], (double)bc);
    }
}

// ---- pool core: one 32x32 source tile -> all 4 pyramid levels (128 thr) ----
__device__ __forceinline__ void pool_block(
    ull* smem_raw, const float* __restrict__ A, const float* __restrict__ B,
    int pb)
{
    float* sm  = reinterpret_cast<float*>(smem_raw);
    float* hA  = sm;            // 32*17 = 544
    float* hB  = sm + 544;
    float* l1A = sm + 1088;     // 16*17 = 272
    float* l1B = sm + 1360;
    float* l2A = sm + 1632;     // 8*9 = 72
    float* l2B = sm + 1704;
    float* l3A = sm + 1776;     // 4*5 = 20
    float* l3B = sm + 1796;

    const int tx = pb & 15;
    const int ty = (pb >> 4) & 15;
    const int z  = pb >> 8;
    const int t = threadIdx.x;

    // load 32x32 tile of both images, fold horizontal pairs
    #pragma unroll
    for (int i = t; i < 256; i += 128) {
        int r = i >> 3, c4 = i & 7;
        size_t src = (((size_t)z * 512) + ty * 32 + r) * 512 + tx * 32 + c4 * 4;
        float4 a = *(const float4*)(A + src);
        float4 b = *(const float4*)(B + src);
        hA[r * 17 + c4 * 2]     = a.x + a.y;
        hA[r * 17 + c4 * 2 + 1] = a.z + a.w;
        hB[r * 17 + c4 * 2]     = b.x + b.y;
        hB[r * 17 + c4 * 2 + 1] = b.z + b.w;
    }
    __syncthreads();

    // L1: 16x16
    #pragma unroll
    for (int i = t; i < 256; i += 128) {
        int y = i >> 4, x = i & 15;
        float va = 0.25f * (hA[2 * y * 17 + x] + hA[(2 * y + 1) * 17 + x]);
        float vb = 0.25f * (hB[2 * y * 17 + x] + hB[(2 * y + 1) * 17 + x]);
        l1A[y * 17 + x] = va; l1B[y * 17 + x] = vb;
        size_t o = (((size_t)z * 256) + ty * 16 + y) * 256 + tx * 16 + x;
        g_p1[O1 + o] = va;
        g_p2[O1 + o] = vb;
    }
    __syncthreads();

    // L2: 8x8
    if (t < 64) {
        const int y = t >> 3, x = t & 7;
        float va = 0.25f * (l1A[2*y*17 + 2*x] + l1A[2*y*17 + 2*x+1] +
                            l1A[(2*y+1)*17 + 2*x] + l1A[(2*y+1)*17 + 2*x+1]);
        float vb = 0.25f * (l1B[2*y*17 + 2*x] + l1B[2*y*17 + 2*x+1] +
                            l1B[(2*y+1)*17 + 2*x] + l1B[(2*y+1)*17 + 2*x+1]);
        l2A[y * 9 + x] = va; l2B[y * 9 + x] = vb;
        size_t o = (((size_t)z * 128) + ty * 8 + y) * 128 + tx * 8 + x;
        g_p1[O2 + o] = va;
        g_p2[O2 + o] = vb;
    }
    __syncthreads();

    // L3: 4x4
    if (t < 16) {
        const int y = t >> 2, x = t & 3;
        float va = 0.25f * (l2A[2*y*9 + 2*x] + l2A[2*y*9 + 2*x+1] +
                            l2A[(2*y+1)*9 + 2*x] + l2A[(2*y+1)*9 + 2*x+1]);
        float vb = 0.25f * (l2B[2*y*9 + 2*x] + l2B[2*y*9 + 2*x+1] +
                            l2B[(2*y+1)*9 + 2*x] + l2B[(2*y+1)*9 + 2*x+1]);
        l3A[y * 5 + x] = va; l3B[y * 5 + x] = vb;
        size_t o = (((size_t)z * 64) + ty * 4 + y) * 64 + tx * 4 + x;
        g_p1[O3 + o] = va;
        g_p2[O3 + o] = vb;
    }
    __syncthreads();

    // L4: 2x2
    if (t < 4) {
        const int y = t >> 1, x = t & 1;
        float va = 0.25f * (l3A[2*y*5 + 2*x] + l3A[2*y*5 + 2*x+1] +
                            l3A[(2*y+1)*5 + 2*x] + l3A[(2*y+1)*5 + 2*x+1]);
        float vb = 0.25f * (l3B[2*y*5 + 2*x] + l3B[2*y*5 + 2*x+1] +
                            l3B[(2*y+1)*5 + 2*x] + l3B[(2*y+1)*5 + 2*x+1]);
        size_t o = (((size_t)z * 32) + ty * 2 + y) * 32 + tx * 2 + x;
        g_p1[O4 + o] = va;
        g_p2[O4 + o] = vb;
    }
}

// ---- kernel 1: ssim L0 (3744 blocks) interleaved 1:3 with pool (12288) ----
__global__ void __launch_bounds__(OC, 6)
k1_kernel(const float* __restrict__ img1, const float* __restrict__ img2) {
    __shared__ ull smem_raw[IR * ICW];
    const int bid = blockIdx.x;
    int pb;
    if (bid < K1_IL) {
        const int g = bid >> 2, lane = bid & 3;
        if (lane == 0) {
            // ssim L0 block g (GX=4, GY=21)
            const int bx = g & 3;
            const int t1 = g >> 2;
            ssim_block(smem_raw, img1, img2, 512, bx, t1 % 21, t1 / 21, 0);
            return;
        }
        pb = g * 3 + lane - 1;              // 0 .. 11231
    } else {
        pb = 11232 + (bid - K1_IL);         // 11232 .. 12287
    }
    pool_block(smem_raw, img1, img2, pb);
}

// ---- kernel 2: 288 relocated L0 blocks + ssim levels 1-4 (= 2.0 waves) ----
__global__ void __launch_bounds__(OC, 6)
k2_kernel(const float* __restrict__ img1, const float* __restrict__ img2) {
    __shared__ ull smem_raw[IR * ICW];
    int lid = blockIdx.x;
    if (lid < K2_SSIM0) {
        const int g = K1_SSIM + lid;        // L0 blocks 3744..4031
        const int bx = g & 3;
        const int t1 = g >> 2;
        ssim_block(smem_raw, img1, img2, 512, bx, t1 % 21, t1 / 21, 0);
        return;
    }
    lid -= K2_SSIM0;
    int level, H, GX, GY;
    if (lid < NB1)                    { level = 1; H = 256; GX = 2; GY = 11; }
    else if ((lid -= NB1) < NB2)      { level = 2; H = 128; GX = 1; GY = 5;  }
    else if ((lid -= NB2) < NB3)      { level = 3; H = 64;  GX = 1; GY = 3;  }
    else { lid -= NB3;                  level = 4; H = 32;  GX = 1; GY = 1;  }
    const int bx = lid % GX;
    const int t1 = lid / GX;
    const int by = t1 % GY;
    const int z  = t1 / GY;
    const unsigned off = (level == 1) ? O1 : (level == 2) ? O2
                       : (level == 3) ? O3 : O4;
    ssim_block(smem_raw, g_p1 + off, g_p2 + off, H, bx, by, z, level);
}

// fp32 combine via log2/exp2 (values in (0.9, 1.0]; rel. err ~1e-7 << 1e-3)
__global__ void final_kernel(float* __restrict__ out) {
    const float Hl[5] = {502.f, 246.f, 118.f, 54.f, 22.f};
    const float Wt[5] = {0.0448f, 0.2856f, 0.3001f, 0.2363f, 0.1333f};
    float lsum = 0.f;
    #pragma unroll
    for (int l = 0; l < 5; l++) {
        float inv_cnt = 1.f / (48.f * Hl[l] * Hl[l]);
        float ms = ((float)g_acc[2 * l]     * inv_cnt + 1.f) * 0.5f;
        float mc = ((float)g_acc[2 * l + 1] * inv_cnt + 1.f) * 0.5f;
        // prod(pow1[:-1] * pow2[-1]): mcs^{w_l} for l<4, mssim4^{4*w_4}
        float x = (l < 4) ? mc : ms;
        float w = (l < 4) ? Wt[l] : 4.f * Wt[4];
        lsum += w * log2f(x);
    }
    out[0] = exp2f(lsum);
}

extern "C" void kernel_launch(void* const* d_in, const int* in_sizes, int n_in,
                              void* d_out, int out_size) {
    const float* img1 = (const float*)d_in[0];
    const float* img2 = (const float*)d_in[1];
    float* out = (float*)d_out;

    double* acc;
    cudaGetSymbolAddress((void**)&acc, g_acc);
    cudaMemsetAsync(acc, 0, 10 * sizeof(double));

    k1_kernel<<<K1_GRID, OC>>>(img1, img2);   // ssim L0 + pool, overlapped
    k2_kernel<<<K2_GRID, OC>>>(img1, img2);   // ssim L1-4 + 288 L0 (2 waves)
    final_kernel<<<1, 1>>>(out);
}